// round 11
// baseline (speedup 1.0000x reference)
#include <cuda_runtime.h>
#include <math.h>
#include <stdint.h>

#define K 5
#define NF 16                 // 15 sym wsc entries + merged (tkl+nlp) feature
#define THREADS 128
#define TILE 256              // 2 SNPs per thread
#define NWARP (THREADS / 32)
#define NBLK 592              // 148 SMs * 4 blocks = one wave
#define LOG2PI_F 1.8378770664093453f

#define INV_F (TILE * 25)               // 6400 floats = 25600 B per buffer
#define DSMEM_BYTES (2 * INV_F * 4)     // 51200 B (double buffer, inv only)

typedef unsigned long long u64;

// per-block partials: [m, S, F[0..15]]
__device__ float g_scratch[NBLK * (NF + 2)];
__device__ int g_count = 0;

__device__ __forceinline__ int pidx(int i, int j) {   // packed upper (i<=j)
    return i * K - (i * (i + 1)) / 2 + j;
}
__device__ __forceinline__ int lidx(int i, int j) {   // packed strict-lower (i>j)
    return i * (i - 1) / 2 + j;
}

// ---- f32x2 packed helpers (sm_100+) ----
__device__ __forceinline__ u64 pack2(float lo, float hi) {
    u64 r; asm("mov.b64 %0, {%1, %2};" : "=l"(r) : "f"(lo), "f"(hi)); return r;
}
__device__ __forceinline__ void unpack2(u64 v, float& lo, float& hi) {
    asm("mov.b64 {%0, %1}, %2;" : "=f"(lo), "=f"(hi) : "l"(v));
}
__device__ __forceinline__ u64 fma2(u64 a, u64 b, u64 c) {
    u64 d; asm("fma.rn.f32x2 %0, %1, %2, %3;" : "=l"(d) : "l"(a), "l"(b), "l"(c)); return d;
}
__device__ __forceinline__ u64 mul2(u64 a, u64 b) {
    u64 d; asm("mul.rn.f32x2 %0, %1, %2;" : "=l"(d) : "l"(a), "l"(b)); return d;
}
__device__ __forceinline__ u64 add2(u64 a, u64 b) {
    u64 d; asm("add.rn.f32x2 %0, %1, %2;" : "=l"(d) : "l"(a), "l"(b)); return d;
}

// ---- mbarrier / TMA bulk helpers ----
__device__ __forceinline__ void mbar_init(uint32_t addr, uint32_t count) {
    asm volatile("mbarrier.init.shared::cta.b64 [%0], %1;" :: "r"(addr), "r"(count) : "memory");
}
__device__ __forceinline__ void mbar_expect_tx(uint32_t addr, uint32_t bytes) {
    asm volatile("mbarrier.arrive.expect_tx.shared::cta.b64 _, [%0], %1;"
                 :: "r"(addr), "r"(bytes) : "memory");
}
__device__ __forceinline__ void bulk_g2s(uint32_t dst, const void* src,
                                         uint32_t bytes, uint32_t mbar) {
    asm volatile(
        "cp.async.bulk.shared::cta.global.mbarrier::complete_tx::bytes [%0], [%1], %2, [%3];"
        :: "r"(dst), "l"(src), "r"(bytes), "r"(mbar) : "memory");
}
__device__ __forceinline__ void mbar_wait(uint32_t addr, uint32_t parity) {
    asm volatile(
        "{\n\t"
        ".reg .pred P1;\n\t"
        "WAIT_%=:\n\t"
        "mbarrier.try_wait.parity.acquire.cta.shared::cta.b64 P1, [%0], %1, 0x989680;\n\t"
        "@P1 bra.uni DONE_%=;\n\t"
        "bra.uni WAIT_%=;\n\t"
        "DONE_%=:\n\t"
        "}"
        :: "r"(addr), "r"(parity) : "memory");
}

extern __shared__ float dynsmem[];

__global__ void __launch_bounds__(THREADS, 4)
fused_kernel(const float* __restrict__ beta_hat,
             const float* __restrict__ inv_shat2,
             const float* __restrict__ pi,
             const float* __restrict__ effect_covar,
             const int* __restrict__ l_iter,
             float* __restrict__ out, int out_size, int P) {
    __shared__ __align__(8) uint64_t mbar[2];
    __shared__ __align__(8) u64 sPriNeg2[15];   // packed (-Pri, -Pri)
    __shared__ float sLdPrior;
    __shared__ float wmaxs[NWARP];
    __shared__ float wf[NWARP][NF + 1];
    __shared__ double dws[NWARP][NF + 1];
    __shared__ float res[K * K];
    __shared__ float klsh;
    __shared__ int isLast;

    const int tid = threadIdx.x;
    const int lane = tid & 31;
    const int wid = tid >> 5;
    const uint32_t mbarAddr = (uint32_t)__cvta_generic_to_shared(&mbar[0]);
    const uint32_t bufAddr = (uint32_t)__cvta_generic_to_shared(dynsmem);

    // ---- init mbarriers + per-block prior inversion (thread 0) ----
    if (tid == 0) {
        mbar_init(mbarAddr, 1);
        mbar_init(mbarAddr + 8, 1);

        const int l = *l_iter;
        const float* Pc = effect_covar + l * K * K;
        float A[K][K], Lm[K][K], Li[K][K];
        for (int i = 0; i < K; i++)
            for (int j = 0; j < K; j++) A[i][j] = Pc[i * K + j];
        float ld = 0.0f;
        for (int j = 0; j < K; j++) {
            float s = A[j][j];
            for (int k = 0; k < j; k++) s -= Lm[j][k] * Lm[j][k];
            ld += __logf(s);
            float il = rsqrtf(s);
            Lm[j][j] = s * il;
            for (int i = j + 1; i < K; i++) {
                float t = A[i][j];
                for (int k = 0; k < j; k++) t -= Lm[i][k] * Lm[j][k];
                Lm[i][j] = t * il;
            }
        }
        for (int j = 0; j < K; j++) {
            Li[j][j] = 1.0f / Lm[j][j];
            for (int i = j + 1; i < K; i++) {
                float t = 0.0f;
                for (int k = j; k < i; k++) t += Lm[i][k] * Li[k][j];
                Li[i][j] = -t / Lm[i][i];
            }
        }
        for (int i = 0; i < K; i++)
            for (int j = i; j < K; j++) {
                float t = 0.0f;
                for (int k = j; k < K; k++) t += Li[k][i] * Li[k][j];
                const float nt = -t;
                sPriNeg2[pidx(i, j)] = pack2(nt, nt);
            }
        sLdPrior = ld;
    }
    __syncthreads();

    const float c15 = 0.5f * (sLdPrior + (float)K * LOG2PI_F);
    const float cz = 0.5f * (float)K * LOG2PI_F;
    const u64 NEG1_2 = pack2(-1.0f, -1.0f);
    const u64 NEGHALF_2 = pack2(-0.5f, -0.5f);
    const u64 C15_2 = pack2(c15, c15);

    // merged-lane online softmax state (scalar accumulators)
    float m = -1e30f, S = 0.0f;
    float F[NF];
#pragma unroll
    for (int j = 0; j < NF; j++) F[j] = 0.0f;

    const int ntiles = (P + TILE - 1) / TILE;

    auto stage = [&](int tile, int b) {
        if (tid != 0) return;
        const int rem = min(TILE, P - tile * TILE);
        const uint32_t invBytes = ((uint32_t)(rem * 100)) & ~15u;
        const uint32_t mb = mbarAddr + (uint32_t)b * 8u;
        const uint32_t dstInv = bufAddr + (uint32_t)(b * INV_F) * 4u;
        mbar_expect_tx(mb, invBytes);
        bulk_g2s(dstInv, inv_shat2 + (size_t)tile * INV_F, invBytes, mb);
    };

    int t = blockIdx.x;
    int cur = 0;
    uint32_t ph0 = 0, ph1 = 0;
    if (t < ntiles) stage(t, 0);

    for (; t < ntiles; t += gridDim.x) {
        const int tn = t + gridDim.x;
        if (tn < ntiles) stage(tn, cur ^ 1);

        mbar_wait(mbarAddr + (uint32_t)cur * 8u, cur ? ph1 : ph0);
        if (cur) ph1 ^= 1; else ph0 ^= 1;

        const float* sInv = dynsmem + cur * INV_F;

        const int la = 2 * tid;            // local SNP a
        const int lb = la + 1;             // local SNP b
        const int p0 = t * TILE + la;      // P even -> pair never straddles P
        if (p0 < P) {
            const int rem = min(TILE, P - t * TILE);
            const int stInvF = (int)(((uint32_t)(rem * 100)) & ~15u) >> 2;
            const bool gf = ((lb + 1) * 25 > stInvF);

            u64 invd[K];
            if (gf) {
#pragma unroll
                for (int k = 0; k < K; k++)
                    invd[k] = pack2(__ldg(&inv_shat2[(size_t)p0 * 25 + k * 6]),
                                    __ldg(&inv_shat2[(size_t)(p0 + 1) * 25 + k * 6]));
            } else {
#pragma unroll
                for (int k = 0; k < K; k++)
                    invd[k] = pack2(sInv[la * 25 + k * 6], sInv[lb * 25 + k * 6]);
            }
            // beta for the pair: 10 consecutive floats, coalesced float2 LDGs
            u64 r[K];
            {
                const float2* b2 = (const float2*)(beta_hat + (size_t)p0 * 5);
                const float2 v0 = __ldg(&b2[0]);
                const float2 v1 = __ldg(&b2[1]);
                const float2 v2 = __ldg(&b2[2]);
                const float2 v3 = __ldg(&b2[3]);
                const float2 v4 = __ldg(&b2[4]);
                // lo SNP = elems 0..4, hi SNP = elems 5..9
                r[0] = pack2(v0.x, v2.y);
                r[1] = pack2(v0.y, v3.x);
                r[2] = pack2(v1.x, v3.y);
                r[3] = pack2(v1.y, v4.x);
                r[4] = pack2(v2.x, v4.y);
            }

            // ---- Cholesky of A = Pri + diag(invd) (packed, neg-free) ----
            u64 Loff[10], iLd[K], niLd[K];
            u64 prod2 = pack2(1.0f, 1.0f);
#pragma unroll
            for (int j = 0; j < K; j++) {
                u64 acc = fma2(invd[j], NEG1_2, sPriNeg2[pidx(j, j)]);
#pragma unroll
                for (int k = 0; k < j; k++)
                    acc = fma2(Loff[lidx(j, k)], Loff[lidx(j, k)], acc);
                const u64 s2 = mul2(acc, NEG1_2);
                prod2 = mul2(prod2, s2);
                float sl, sh; unpack2(s2, sl, sh);
                iLd[j] = pack2(rsqrtf(sl), rsqrtf(sh));
                niLd[j] = mul2(iLd[j], NEG1_2);
#pragma unroll
                for (int i = j + 1; i < K; i++) {
                    u64 a2 = sPriNeg2[pidx(j, i)];
#pragma unroll
                    for (int k = 0; k < j; k++)
                        a2 = fma2(Loff[lidx(i, k)], Loff[lidx(j, k)], a2);
                    Loff[lidx(i, j)] = mul2(a2, niLd[j]);
                }
            }

            // r = beta .* invd
#pragma unroll
            for (int k = 0; k < K; k++) r[k] = mul2(r[k], invd[k]);

            // forward then backward solve (neg-absorbed), y := mu
            u64 y[K];
#pragma unroll
            for (int j = 0; j < K; j++) {
                u64 acc = mul2(r[j], NEG1_2);
#pragma unroll
                for (int k = 0; k < j; k++) acc = fma2(Loff[lidx(j, k)], y[k], acc);
                y[j] = mul2(acc, niLd[j]);
            }
#pragma unroll
            for (int j = K - 1; j >= 0; j--) {
                u64 acc = mul2(y[j], NEG1_2);
#pragma unroll
                for (int k = j + 1; k < K; k++) acc = fma2(Loff[lidx(k, j)], y[k], acc);
                y[j] = mul2(acc, niLd[j]);
            }
            u64 maha2 = mul2(y[0], r[0]);
#pragma unroll
            for (int k = 1; k < K; k++) maha2 = fma2(y[k], r[k], maha2);

            // in-place invert L: Loff -> strict-lower of L^-1
#pragma unroll
            for (int j = 0; j < K; j++) {
#pragma unroll
                for (int i = j + 1; i < K; i++) {
                    u64 t2 = mul2(Loff[lidx(i, j)], iLd[j]);
#pragma unroll
                    for (int k = j + 1; k < i; k++)
                        t2 = fma2(Loff[lidx(i, k)], Loff[lidx(k, j)], t2);
                    Loff[lidx(i, j)] = mul2(t2, niLd[i]);
                }
            }

            // diag features fd_i = Sigma_ii + mu_i^2 ; dsum = sum invd*fd
            u64 fd[K];
#pragma unroll
            for (int i = 0; i < K; i++) {
                u64 t2 = fma2(y[i], y[i], mul2(iLd[i], iLd[i]));
#pragma unroll
                for (int k = i + 1; k < K; k++)
                    t2 = fma2(Loff[lidx(k, i)], Loff[lidx(k, i)], t2);
                fd[i] = t2;
            }
            u64 dsum2 = mul2(invd[0], fd[0]);
#pragma unroll
            for (int i = 1; i < K; i++) dsum2 = fma2(invd[i], fd[i], dsum2);

            // f15 = maha + c15 - 0.5*dsum
            const u64 f15_2 = fma2(dsum2, NEGHALF_2, add2(maha2, C15_2));

            // z per lane (scalar MUFU)
            float pl, ph2; unpack2(prod2, pl, ph2);
            float mal, mah; unpack2(maha2, mal, mah);
            float pil, pih;
            {
                const float2 pv = __ldg((const float2*)(pi + p0));
                pil = pv.x; pih = pv.y;
            }
            const float z_l = __logf(pil) + cz + 0.5f * (mal - __logf(pl));
            const float z_h = __logf(pih) + cz + 0.5f * (mah - __logf(ph2));

            // merged-lane online softmax: one running max for both lanes
            const float newm = fmaxf(m, fmaxf(z_l, z_h));
            const float sc = __expf(m - newm);
            const float wl = __expf(z_l - newm);
            const float wh = __expf(z_h - newm);
            m = newm;
            S = S * sc + wl + wh;
            const u64 w2 = pack2(wl, wh);

            // per-feature: F = F*sc + wl*f_l + wh*f_h  (dot of packed halves)
            {
                float fl, fh;
                unpack2(mul2(w2, fd[0]), fl, fh);  F[0]  = F[0]  * sc + fl + fh;
                unpack2(mul2(w2, fd[1]), fl, fh);  F[5]  = F[5]  * sc + fl + fh;
                unpack2(mul2(w2, fd[2]), fl, fh);  F[9]  = F[9]  * sc + fl + fh;
                unpack2(mul2(w2, fd[3]), fl, fh);  F[12] = F[12] * sc + fl + fh;
                unpack2(mul2(w2, fd[4]), fl, fh);  F[14] = F[14] * sc + fl + fh;
                unpack2(mul2(w2, f15_2), fl, fh);  F[15] = F[15] * sc + fl + fh;
            }
#pragma unroll
            for (int i = 0; i < K; i++) {
#pragma unroll
                for (int j = i + 1; j < K; j++) {
                    u64 t2 = fma2(y[i], y[j], mul2(Loff[lidx(j, i)], iLd[j]));
#pragma unroll
                    for (int k = j + 1; k < K; k++)
                        t2 = fma2(Loff[lidx(k, i)], Loff[lidx(k, j)], t2);
                    float fl, fh; unpack2(mul2(w2, t2), fl, fh);
                    const int q = pidx(i, j);
                    F[q] = F[q] * sc + fl + fh;
                }
            }
        }
        __syncthreads();   // all reads done before buffer is re-staged
        cur ^= 1;
    }

    // ---- block reduction ----
    float bm = m;
#pragma unroll
    for (int o = 16; o; o >>= 1) bm = fmaxf(bm, __shfl_xor_sync(0xFFFFFFFFu, bm, o));
    if (lane == 0) wmaxs[wid] = bm;
    __syncthreads();
    float Mb = wmaxs[0];
#pragma unroll
    for (int q = 1; q < NWARP; q++) Mb = fmaxf(Mb, wmaxs[q]);

    const float w0 = __expf(m - Mb);
    float vals[NF + 1];
    vals[0] = S * w0;
#pragma unroll
    for (int j = 0; j < NF; j++) vals[1 + j] = F[j] * w0;
#pragma unroll
    for (int j = 0; j < NF + 1; j++) {
#pragma unroll
        for (int o = 16; o; o >>= 1) vals[j] += __shfl_xor_sync(0xFFFFFFFFu, vals[j], o);
    }
    if (lane == 0) {
#pragma unroll
        for (int j = 0; j < NF + 1; j++) wf[wid][j] = vals[j];
    }
    __syncthreads();
    if (wid == 0) {
        float acc[NF + 1];
#pragma unroll
        for (int j = 0; j < NF + 1; j++) acc[j] = (lane < NWARP) ? wf[lane][j] : 0.0f;
#pragma unroll
        for (int j = 0; j < NF + 1; j++) {
#pragma unroll
            for (int o = 2; o; o >>= 1) acc[j] += __shfl_xor_sync(0xFFFFFFFFu, acc[j], o);
        }
        if (lane == 0) {
            float* dst = &g_scratch[blockIdx.x * (NF + 2)];
            dst[0] = Mb;
#pragma unroll
            for (int j = 0; j < NF + 1; j++) dst[1 + j] = acc[j];
        }
    }

    // ---- last-block finalize ----
    __threadfence();
    if (tid == 0) {
        const int old = atomicAdd(&g_count, 1);
        isLast = (old == (int)gridDim.x - 1) ? 1 : 0;
    }
    __syncthreads();
    if (!isLast) return;
    __threadfence();

    float lm = -1e30f;
    for (int b2 = tid; b2 < NBLK; b2 += THREADS) lm = fmaxf(lm, g_scratch[b2 * (NF + 2)]);
#pragma unroll
    for (int o = 16; o; o >>= 1) lm = fmaxf(lm, __shfl_xor_sync(0xFFFFFFFFu, lm, o));
    if (lane == 0) wmaxs[wid] = lm;
    __syncthreads();
    float M = wmaxs[0];
#pragma unroll
    for (int q = 1; q < NWARP; q++) M = fmaxf(M, wmaxs[q]);

    double acc[NF + 1];
#pragma unroll
    for (int j = 0; j < NF + 1; j++) acc[j] = 0.0;
    for (int b2 = tid; b2 < NBLK; b2 += THREADS) {
        const float* sc2p = &g_scratch[b2 * (NF + 2)];
        const double wgt = exp((double)(sc2p[0] - M));
        acc[0] += wgt * (double)sc2p[1];
#pragma unroll
        for (int j = 0; j < NF; j++) acc[1 + j] += wgt * (double)sc2p[2 + j];
    }
#pragma unroll
    for (int j = 0; j < NF + 1; j++) {
#pragma unroll
        for (int o = 16; o; o >>= 1) acc[j] += __shfl_xor_sync(0xFFFFFFFFu, acc[j], o);
    }
    if (lane == 0) {
#pragma unroll
        for (int j = 0; j < NF + 1; j++) dws[wid][j] = acc[j];
    }
    __syncthreads();
    if (tid == 0) {
        double tot[NF + 1];
#pragma unroll
        for (int j = 0; j < NF + 1; j++) {
            double tt = 0.0;
            for (int q = 0; q < NWARP; q++) tt += dws[q][j];
            tot[j] = tt;
        }
        const double Stot = tot[0];
        const double lse = (double)M + log(Stot);
        int idx = 0;
        for (int i = 0; i < K; i++)
            for (int j = i; j < K; j++) {
                const float v = (float)(tot[1 + idx] / Stot);
                res[i * K + j] = v;
                res[j * K + i] = v;
                idx++;
            }
        klsh = (float)(tot[1 + 15] / Stot - lse);
    }
    __syncthreads();

    const int n_eff = out_size - 1;
    for (int i = tid; i < n_eff; i += THREADS) out[i] = effect_covar[i];
    __syncthreads();
    const int l = *l_iter;
    if (tid < K * K) out[l * K * K + tid] = res[tid];
    if (tid == 0) {
        out[out_size - 1] = klsh;
        g_count = 0;  // reset for next graph replay
    }
}

// ---------------------------------------------------------------------------
extern "C" void kernel_launch(void* const* d_in, const int* in_sizes, int n_in,
                              void* d_out, int out_size) {
    const float* beta_hat = (const float*)d_in[0];
    // d_in[1] = shat2 (unused: diagonal, inverse available)
    const float* inv_shat2 = (const float*)d_in[2];
    const float* pi = (const float*)d_in[3];
    const float* effect_covar = (const float*)d_in[4];
    const int* l_iter = (const int*)d_in[5];
    float* out = (float*)d_out;

    const int P = in_sizes[0] / K;

    static int smem_set = 0;
    if (!smem_set) {
        cudaFuncSetAttribute(fused_kernel,
                             cudaFuncAttributeMaxDynamicSharedMemorySize,
                             DSMEM_BYTES);
        smem_set = 1;
    }

    fused_kernel<<<NBLK, THREADS, DSMEM_BYTES>>>(beta_hat, inv_shat2, pi,
                                                 effect_covar, l_iter, out,
                                                 out_size, P);
}

// round 14
// speedup vs baseline: 1.0966x; 1.0966x over previous
#include <cuda_runtime.h>
#include <math.h>
#include <stdint.h>

#define K 5
#define NF 16                 // 15 sym wsc entries + merged (tkl+nlp) feature
#define THREADS 128
#define TILE 256              // 2 SNPs per thread
#define NWARP (THREADS / 32)
#define NBLK 444              // 148 SMs * 3 blocks = one wave
#define LOG2PI_F 1.8378770664093453f

#define INV_F (TILE * 25)     // 6400 floats = 25600 B
#define BETA_F (TILE * 5)     // 1280 floats = 5120 B
#define BUF_F (INV_F + BETA_F)          // 7680 floats
#define DSMEM_BYTES (2 * BUF_F * 4)     // 61440 B

typedef unsigned long long u64;

// per-block partials: [m, S, F[0..15]]
__device__ float g_scratch[NBLK * (NF + 2)];
__device__ int g_count = 0;

__device__ __forceinline__ int pidx(int i, int j) {   // packed upper (i<=j)
    return i * K - (i * (i + 1)) / 2 + j;
}
__device__ __forceinline__ int lidx(int i, int j) {   // packed strict-lower (i>j)
    return i * (i - 1) / 2 + j;
}

// ---- f32x2 packed helpers (sm_100+) ----
__device__ __forceinline__ u64 pack2(float lo, float hi) {
    u64 r; asm("mov.b64 %0, {%1, %2};" : "=l"(r) : "f"(lo), "f"(hi)); return r;
}
__device__ __forceinline__ void unpack2(u64 v, float& lo, float& hi) {
    asm("mov.b64 {%0, %1}, %2;" : "=f"(lo), "=f"(hi) : "l"(v));
}
__device__ __forceinline__ u64 fma2(u64 a, u64 b, u64 c) {
    u64 d; asm("fma.rn.f32x2 %0, %1, %2, %3;" : "=l"(d) : "l"(a), "l"(b), "l"(c)); return d;
}
__device__ __forceinline__ u64 mul2(u64 a, u64 b) {
    u64 d; asm("mul.rn.f32x2 %0, %1, %2;" : "=l"(d) : "l"(a), "l"(b)); return d;
}
__device__ __forceinline__ u64 add2(u64 a, u64 b) {
    u64 d; asm("add.rn.f32x2 %0, %1, %2;" : "=l"(d) : "l"(a), "l"(b)); return d;
}

// ---- L2 persistence policy ----
__device__ __forceinline__ u64 mk_evict_last_policy() {
    u64 p;
    asm("createpolicy.fractional.L2::evict_last.b64 %0, 1.0;" : "=l"(p));
    return p;
}

// ---- mbarrier / TMA bulk helpers ----
__device__ __forceinline__ void mbar_init(uint32_t addr, uint32_t count) {
    asm volatile("mbarrier.init.shared::cta.b64 [%0], %1;" :: "r"(addr), "r"(count) : "memory");
}
__device__ __forceinline__ void mbar_expect_tx(uint32_t addr, uint32_t bytes) {
    asm volatile("mbarrier.arrive.expect_tx.shared::cta.b64 _, [%0], %1;"
                 :: "r"(addr), "r"(bytes) : "memory");
}
__device__ __forceinline__ void bulk_g2s_policy(uint32_t dst, const void* src,
                                                uint32_t bytes, uint32_t mbar, u64 pol) {
    asm volatile(
        "cp.async.bulk.shared::cta.global.mbarrier::complete_tx::bytes.L2::cache_hint"
        " [%0], [%1], %2, [%3], %4;"
        :: "r"(dst), "l"(src), "r"(bytes), "r"(mbar), "l"(pol) : "memory");
}
__device__ __forceinline__ void mbar_wait(uint32_t addr, uint32_t parity) {
    asm volatile(
        "{\n\t"
        ".reg .pred P1;\n\t"
        "WAIT_%=:\n\t"
        "mbarrier.try_wait.parity.acquire.cta.shared::cta.b64 P1, [%0], %1, 0x989680;\n\t"
        "@P1 bra.uni DONE_%=;\n\t"
        "bra.uni WAIT_%=;\n\t"
        "DONE_%=:\n\t"
        "}"
        :: "r"(addr), "r"(parity) : "memory");
}
// pi load with cache-hint policy (policy-register form, ptxas-accepted)
__device__ __forceinline__ float2 ld_pi2_persist(const float* p, u64 pol) {
    float2 v;
    asm("ld.global.nc.L2::cache_hint.v2.f32 {%0, %1}, [%2], %3;"
        : "=f"(v.x), "=f"(v.y) : "l"(p), "l"(pol));
    return v;
}

extern __shared__ float dynsmem[];

__global__ void __launch_bounds__(THREADS, 3)
fused_kernel(const float* __restrict__ beta_hat,
             const float* __restrict__ inv_shat2,
             const float* __restrict__ pi,
             const float* __restrict__ effect_covar,
             const int* __restrict__ l_iter,
             float* __restrict__ out, int out_size, int P) {
    __shared__ __align__(8) uint64_t mbar[2];
    __shared__ __align__(8) u64 sPriNeg2[15];   // packed (-Pri, -Pri)
    __shared__ float sLdPrior;
    __shared__ float wmaxs[NWARP];
    __shared__ float wf[NWARP][NF + 1];
    __shared__ double dws[NWARP][NF + 1];
    __shared__ float res[K * K];
    __shared__ float klsh;
    __shared__ int isLast;

    const int tid = threadIdx.x;
    const int lane = tid & 31;
    const int wid = tid >> 5;
    const uint32_t mbarAddr = (uint32_t)__cvta_generic_to_shared(&mbar[0]);
    const uint32_t bufAddr = (uint32_t)__cvta_generic_to_shared(dynsmem);
    const u64 l2pol = mk_evict_last_policy();

    // ---- init mbarriers + per-block prior inversion (thread 0) ----
    if (tid == 0) {
        mbar_init(mbarAddr, 1);
        mbar_init(mbarAddr + 8, 1);

        const int l = *l_iter;
        const float* Pc = effect_covar + l * K * K;
        float A[K][K], Lm[K][K], Li[K][K];
        for (int i = 0; i < K; i++)
            for (int j = 0; j < K; j++) A[i][j] = Pc[i * K + j];
        float ld = 0.0f;
        for (int j = 0; j < K; j++) {
            float s = A[j][j];
            for (int k = 0; k < j; k++) s -= Lm[j][k] * Lm[j][k];
            ld += __logf(s);
            float il = rsqrtf(s);
            Lm[j][j] = s * il;
            for (int i = j + 1; i < K; i++) {
                float t = A[i][j];
                for (int k = 0; k < j; k++) t -= Lm[i][k] * Lm[j][k];
                Lm[i][j] = t * il;
            }
        }
        for (int j = 0; j < K; j++) {
            Li[j][j] = 1.0f / Lm[j][j];
            for (int i = j + 1; i < K; i++) {
                float t = 0.0f;
                for (int k = j; k < i; k++) t += Lm[i][k] * Li[k][j];
                Li[i][j] = -t / Lm[i][i];
            }
        }
        for (int i = 0; i < K; i++)
            for (int j = i; j < K; j++) {
                float t = 0.0f;
                for (int k = j; k < K; k++) t += Li[k][i] * Li[k][j];
                const float nt = -t;
                sPriNeg2[pidx(i, j)] = pack2(nt, nt);
            }
        sLdPrior = ld;
    }
    __syncthreads();

    const float c15 = 0.5f * (sLdPrior + (float)K * LOG2PI_F);
    const float cz = 0.5f * (float)K * LOG2PI_F;
    const u64 NEG1_2 = pack2(-1.0f, -1.0f);
    const u64 NEGHALF_2 = pack2(-0.5f, -0.5f);
    const u64 C15_2 = pack2(c15, c15);

    float m_l = -1e30f, m_h = -1e30f;
    u64 S2 = 0ull;
    u64 F[NF];
#pragma unroll
    for (int j = 0; j < NF; j++) F[j] = 0ull;

    const int ntiles = (P + TILE - 1) / TILE;

    auto stage = [&](int tile, int b) {
        if (tid != 0) return;
        const int rem = min(TILE, P - tile * TILE);
        const uint32_t invBytes = ((uint32_t)(rem * 100)) & ~15u;
        const uint32_t betaBytes = ((uint32_t)(rem * 20)) & ~15u;
        const uint32_t mb = mbarAddr + (uint32_t)b * 8u;
        const uint32_t dstInv = bufAddr + (uint32_t)(b * BUF_F) * 4u;
        const uint32_t dstBeta = dstInv + (uint32_t)INV_F * 4u;
        mbar_expect_tx(mb, invBytes + betaBytes);
        bulk_g2s_policy(dstInv, inv_shat2 + (size_t)tile * INV_F, invBytes, mb, l2pol);
        bulk_g2s_policy(dstBeta, beta_hat + (size_t)tile * BETA_F, betaBytes, mb, l2pol);
    };

    int t = blockIdx.x;
    int cur = 0;
    uint32_t ph0 = 0, ph1 = 0;
    if (t < ntiles) stage(t, 0);

    for (; t < ntiles; t += gridDim.x) {
        const int tn = t + gridDim.x;
        if (tn < ntiles) stage(tn, cur ^ 1);

        mbar_wait(mbarAddr + (uint32_t)cur * 8u, cur ? ph1 : ph0);
        if (cur) ph1 ^= 1; else ph0 ^= 1;

        const float* sInv = dynsmem + cur * BUF_F;
        const float* sBeta = sInv + INV_F;

        const int la = 2 * tid;            // local SNP a
        const int lb = la + 1;             // local SNP b
        const int p0 = t * TILE + la;      // P even -> pair never straddles P
        if (p0 < P) {
            const int rem = min(TILE, P - t * TILE);
            const int stInvF = (int)(((uint32_t)(rem * 100)) & ~15u) >> 2;
            const int stBetaF = (int)(((uint32_t)(rem * 20)) & ~15u) >> 2;
            const bool gf = ((lb + 1) * 25 > stInvF) || ((lb + 1) * 5 > stBetaF);

            u64 invd[K], r[K];
            if (gf) {
#pragma unroll
                for (int k = 0; k < K; k++) {
                    invd[k] = pack2(__ldg(&inv_shat2[(size_t)p0 * 25 + k * 6]),
                                    __ldg(&inv_shat2[(size_t)(p0 + 1) * 25 + k * 6]));
                    r[k] = pack2(__ldg(&beta_hat[(size_t)p0 * 5 + k]),
                                 __ldg(&beta_hat[(size_t)(p0 + 1) * 5 + k]));
                }
            } else {
#pragma unroll
                for (int k = 0; k < K; k++) {
                    invd[k] = pack2(sInv[la * 25 + k * 6], sInv[lb * 25 + k * 6]);
                    r[k] = pack2(sBeta[la * 5 + k], sBeta[lb * 5 + k]);
                }
            }

            // ---- Cholesky of A = Pri + diag(invd) (packed, neg-free) ----
            u64 Loff[10], iLd[K], niLd[K];
            u64 prod2 = pack2(1.0f, 1.0f);
#pragma unroll
            for (int j = 0; j < K; j++) {
                u64 acc = fma2(invd[j], NEG1_2, sPriNeg2[pidx(j, j)]);
#pragma unroll
                for (int k = 0; k < j; k++)
                    acc = fma2(Loff[lidx(j, k)], Loff[lidx(j, k)], acc);
                const u64 s2 = mul2(acc, NEG1_2);
                prod2 = mul2(prod2, s2);
                float sl, sh; unpack2(s2, sl, sh);
                iLd[j] = pack2(rsqrtf(sl), rsqrtf(sh));
                niLd[j] = mul2(iLd[j], NEG1_2);
#pragma unroll
                for (int i = j + 1; i < K; i++) {
                    u64 a2 = sPriNeg2[pidx(j, i)];
#pragma unroll
                    for (int k = 0; k < j; k++)
                        a2 = fma2(Loff[lidx(i, k)], Loff[lidx(j, k)], a2);
                    Loff[lidx(i, j)] = mul2(a2, niLd[j]);
                }
            }

            // r = beta .* invd
#pragma unroll
            for (int k = 0; k < K; k++) r[k] = mul2(r[k], invd[k]);

            // forward then backward solve (neg-absorbed), y := mu
            u64 y[K];
#pragma unroll
            for (int j = 0; j < K; j++) {
                u64 acc = mul2(r[j], NEG1_2);
#pragma unroll
                for (int k = 0; k < j; k++) acc = fma2(Loff[lidx(j, k)], y[k], acc);
                y[j] = mul2(acc, niLd[j]);
            }
#pragma unroll
            for (int j = K - 1; j >= 0; j--) {
                u64 acc = mul2(y[j], NEG1_2);
#pragma unroll
                for (int k = j + 1; k < K; k++) acc = fma2(Loff[lidx(k, j)], y[k], acc);
                y[j] = mul2(acc, niLd[j]);
            }
            u64 maha2 = mul2(y[0], r[0]);
#pragma unroll
            for (int k = 1; k < K; k++) maha2 = fma2(y[k], r[k], maha2);

            // in-place invert L: Loff -> strict-lower of L^-1
#pragma unroll
            for (int j = 0; j < K; j++) {
#pragma unroll
                for (int i = j + 1; i < K; i++) {
                    u64 t2 = mul2(Loff[lidx(i, j)], iLd[j]);
#pragma unroll
                    for (int k = j + 1; k < i; k++)
                        t2 = fma2(Loff[lidx(i, k)], Loff[lidx(k, j)], t2);
                    Loff[lidx(i, j)] = mul2(t2, niLd[i]);
                }
            }

            // diag features fd_i = Sigma_ii + mu_i^2 ; dsum = sum invd*fd
            u64 fd[K];
#pragma unroll
            for (int i = 0; i < K; i++) {
                u64 t2 = fma2(y[i], y[i], mul2(iLd[i], iLd[i]));
#pragma unroll
                for (int k = i + 1; k < K; k++)
                    t2 = fma2(Loff[lidx(k, i)], Loff[lidx(k, i)], t2);
                fd[i] = t2;
            }
            u64 dsum2 = mul2(invd[0], fd[0]);
#pragma unroll
            for (int i = 1; i < K; i++) dsum2 = fma2(invd[i], fd[i], dsum2);

            // f15 = maha + c15 - 0.5*dsum
            const u64 f15_2 = fma2(dsum2, NEGHALF_2, add2(maha2, C15_2));

            // z per lane (scalar log/exp)
            float pl, ph2; unpack2(prod2, pl, ph2);
            float mal, mah; unpack2(maha2, mal, mah);
            const float2 pv = ld_pi2_persist(pi + p0, l2pol);
            const float z_l = __logf(pv.x) + cz + 0.5f * (mal - __logf(pl));
            const float z_h = __logf(pv.y) + cz + 0.5f * (mah - __logf(ph2));

            const float nml = fmaxf(m_l, z_l);
            const float scl = __expf(m_l - nml);
            const float wl = __expf(z_l - nml);
            m_l = nml;
            const float nmh = fmaxf(m_h, z_h);
            const float sch = __expf(m_h - nmh);
            const float wh = __expf(z_h - nmh);
            m_h = nmh;
            const u64 sc2 = pack2(scl, sch);
            const u64 w2 = pack2(wl, wh);

            S2 = fma2(S2, sc2, w2);
            F[0]  = fma2(F[0],  sc2, mul2(w2, fd[0]));
            F[5]  = fma2(F[5],  sc2, mul2(w2, fd[1]));
            F[9]  = fma2(F[9],  sc2, mul2(w2, fd[2]));
            F[12] = fma2(F[12], sc2, mul2(w2, fd[3]));
            F[14] = fma2(F[14], sc2, mul2(w2, fd[4]));
            F[15] = fma2(F[15], sc2, mul2(w2, f15_2));
            // off-diag Sigma_ij + mu_i mu_j fused into accumulators
#pragma unroll
            for (int i = 0; i < K; i++) {
#pragma unroll
                for (int j = i + 1; j < K; j++) {
                    u64 t2 = fma2(y[i], y[j], mul2(Loff[lidx(j, i)], iLd[j]));
#pragma unroll
                    for (int k = j + 1; k < K; k++)
                        t2 = fma2(Loff[lidx(k, i)], Loff[lidx(k, j)], t2);
                    const int q = pidx(i, j);
                    F[q] = fma2(F[q], sc2, mul2(w2, t2));
                }
            }
        }
        __syncthreads();   // all reads done before buffer is re-staged
        cur ^= 1;
    }

    // ---- merge the two lanes + block reduction ----
    float bm = fmaxf(m_l, m_h);
#pragma unroll
    for (int o = 16; o; o >>= 1) bm = fmaxf(bm, __shfl_xor_sync(0xFFFFFFFFu, bm, o));
    if (lane == 0) wmaxs[wid] = bm;
    __syncthreads();
    float Mb = wmaxs[0];
#pragma unroll
    for (int q = 1; q < NWARP; q++) Mb = fmaxf(Mb, wmaxs[q]);

    const float w0l = __expf(m_l - Mb);
    const float w0h = __expf(m_h - Mb);
    float vals[NF + 1];
    {
        float sl, sh; unpack2(S2, sl, sh);
        vals[0] = sl * w0l + sh * w0h;
    }
#pragma unroll
    for (int j = 0; j < NF; j++) {
        float fl, fh; unpack2(F[j], fl, fh);
        vals[1 + j] = fl * w0l + fh * w0h;
    }
#pragma unroll
    for (int j = 0; j < NF + 1; j++) {
#pragma unroll
        for (int o = 16; o; o >>= 1) vals[j] += __shfl_xor_sync(0xFFFFFFFFu, vals[j], o);
    }
    if (lane == 0) {
#pragma unroll
        for (int j = 0; j < NF + 1; j++) wf[wid][j] = vals[j];
    }
    __syncthreads();
    if (wid == 0) {
        float acc[NF + 1];
#pragma unroll
        for (int j = 0; j < NF + 1; j++) acc[j] = (lane < NWARP) ? wf[lane][j] : 0.0f;
#pragma unroll
        for (int j = 0; j < NF + 1; j++) {
#pragma unroll
            for (int o = 2; o; o >>= 1) acc[j] += __shfl_xor_sync(0xFFFFFFFFu, acc[j], o);
        }
        if (lane == 0) {
            float* dst = &g_scratch[blockIdx.x * (NF + 2)];
            dst[0] = Mb;
#pragma unroll
            for (int j = 0; j < NF + 1; j++) dst[1 + j] = acc[j];
        }
    }

    // ---- last-block finalize ----
    __threadfence();
    if (tid == 0) {
        const int old = atomicAdd(&g_count, 1);
        isLast = (old == (int)gridDim.x - 1) ? 1 : 0;
    }
    __syncthreads();
    if (!isLast) return;
    __threadfence();

    float lm = -1e30f;
    for (int b2 = tid; b2 < NBLK; b2 += THREADS) lm = fmaxf(lm, g_scratch[b2 * (NF + 2)]);
#pragma unroll
    for (int o = 16; o; o >>= 1) lm = fmaxf(lm, __shfl_xor_sync(0xFFFFFFFFu, lm, o));
    if (lane == 0) wmaxs[wid] = lm;
    __syncthreads();
    float M = wmaxs[0];
#pragma unroll
    for (int q = 1; q < NWARP; q++) M = fmaxf(M, wmaxs[q]);

    double acc[NF + 1];
#pragma unroll
    for (int j = 0; j < NF + 1; j++) acc[j] = 0.0;
    for (int b2 = tid; b2 < NBLK; b2 += THREADS) {
        const float* sc2p = &g_scratch[b2 * (NF + 2)];
        const double wgt = exp((double)(sc2p[0] - M));
        acc[0] += wgt * (double)sc2p[1];
#pragma unroll
        for (int j = 0; j < NF; j++) acc[1 + j] += wgt * (double)sc2p[2 + j];
    }
#pragma unroll
    for (int j = 0; j < NF + 1; j++) {
#pragma unroll
        for (int o = 16; o; o >>= 1) acc[j] += __shfl_xor_sync(0xFFFFFFFFu, acc[j], o);
    }
    if (lane == 0) {
#pragma unroll
        for (int j = 0; j < NF + 1; j++) dws[wid][j] = acc[j];
    }
    __syncthreads();
    if (tid == 0) {
        double tot[NF + 1];
#pragma unroll
        for (int j = 0; j < NF + 1; j++) {
            double tt = 0.0;
            for (int q = 0; q < NWARP; q++) tt += dws[q][j];
            tot[j] = tt;
        }
        const double Stot = tot[0];
        const double lse = (double)M + log(Stot);
        int idx = 0;
        for (int i = 0; i < K; i++)
            for (int j = i; j < K; j++) {
                const float v = (float)(tot[1 + idx] / Stot);
                res[i * K + j] = v;
                res[j * K + i] = v;
                idx++;
            }
        klsh = (float)(tot[1 + 15] / Stot - lse);
    }
    __syncthreads();

    const int n_eff = out_size - 1;
    for (int i = tid; i < n_eff; i += THREADS) out[i] = effect_covar[i];
    __syncthreads();
    const int l = *l_iter;
    if (tid < K * K) out[l * K * K + tid] = res[tid];
    if (tid == 0) {
        out[out_size - 1] = klsh;
        g_count = 0;  // reset for next graph replay
    }
}

// ---------------------------------------------------------------------------
extern "C" void kernel_launch(void* const* d_in, const int* in_sizes, int n_in,
                              void* d_out, int out_size) {
    const float* beta_hat = (const float*)d_in[0];
    // d_in[1] = shat2 (unused: diagonal, inverse available)
    const float* inv_shat2 = (const float*)d_in[2];
    const float* pi = (const float*)d_in[3];
    const float* effect_covar = (const float*)d_in[4];
    const int* l_iter = (const int*)d_in[5];
    float* out = (float*)d_out;

    const int P = in_sizes[0] / K;

    static int smem_set = 0;
    if (!smem_set) {
        cudaFuncSetAttribute(fused_kernel,
                             cudaFuncAttributeMaxDynamicSharedMemorySize,
                             DSMEM_BYTES);
        smem_set = 1;
    }

    fused_kernel<<<NBLK, THREADS, DSMEM_BYTES>>>(beta_hat, inv_shat2, pi,
                                                 effect_covar, l_iter, out,
                                                 out_size, P);
}